// round 12
// baseline (speedup 1.0000x reference)
#include <cuda_runtime.h>
#include <cuda_bf16.h>

// out = K * conv3x3(inp, k), K = linear LIF gain (R1 analysis: I < 9 < 14, so
// the 1000-step LIF never clamps and is exactly linear; K computed host-side
// in double).
//
// R11: occupancy push. Three prior kernels all sat at ~25us with NO pipe >52%
// and occ=62% (regs=40 -> 12 blocks/SM). Changes:
//  - weights in __constant__ (graph-capturable D2D cudaMemcpyToSymbolAsync),
//    K applied as post-multiply -> no weight GPRs.
//  - rolling 3-row window (float4 + float2 = 18 data regs).
//  - __launch_bounds__(128, 16): 32-reg cap -> 16 blocks/SM (100% occ).
//  - ROWS=15 (510 = 34*15): grid = 2176 blocks <= 2368 resident -> ONE wave.

#define H_IN 512
#define W_IN 512
#define H_OUT 510
#define W_OUT 510
#define BATCH 64
#define ROWS 15         // output rows per thread (510 = 34 * 15, exact)
#define TPB 128         // each thread covers 4 cols -> 512 >= 510

__constant__ float c_kw[9];

__global__ __launch_bounds__(TPB, 16) void snn_conv_kernel(
    const float* __restrict__ inp,
    float* __restrict__ out,
    float K) {
    const int tx = threadIdx.x;
    const int x  = tx * 4;
    const int y0 = blockIdx.y * ROWS;
    const int n  = blockIdx.z;
    const bool full = (tx != TPB - 1);   // tx==127: no cols 512+, stores 2 cols

    const float* base = inp + ((size_t)n * H_IN + y0) * W_IN + x;

    // rolling 3-row window: float4 (cols x..x+3) + float2 (cols x+4..x+5)
    float4 a[3];
    float2 b[3];

    #pragma unroll
    for (int j = 0; j < 2; j++) {
        const float* p = base + j * W_IN;
        a[j] = *(const float4*)p;
        b[j] = full ? *(const float2*)(p + 4) : make_float2(0.f, 0.f);
    }

    float* obase = out + ((size_t)n * H_OUT + y0) * W_OUT + x;

    #pragma unroll
    for (int r = 0; r < ROWS; r++) {
        // load input row y0 + r + 2 into slot (r+2)%3
        {
            const float* p = base + (r + 2) * W_IN;
            int s = (r + 2) % 3;
            a[s] = *(const float4*)p;
            b[s] = full ? *(const float2*)(p + 4) : make_float2(0.f, 0.f);
        }

        float o0 = 0.f, o1 = 0.f, o2 = 0.f, o3 = 0.f;

        #pragma unroll
        for (int j = 0; j < 3; j++) {
            int s = (r + j) % 3;
            float w0 = c_kw[3 * j + 0];
            float w1 = c_kw[3 * j + 1];
            float w2 = c_kw[3 * j + 2];
            float4 A = a[s];
            float2 B = b[s];
            o0 = fmaf(w0, A.x, o0); o0 = fmaf(w1, A.y, o0); o0 = fmaf(w2, A.z, o0);
            o1 = fmaf(w0, A.y, o1); o1 = fmaf(w1, A.z, o1); o1 = fmaf(w2, A.w, o1);
            o2 = fmaf(w0, A.z, o2); o2 = fmaf(w1, A.w, o2); o2 = fmaf(w2, B.x, o2);
            o3 = fmaf(w0, A.w, o3); o3 = fmaf(w1, B.x, o3); o3 = fmaf(w2, B.y, o3);
        }

        // direct paired STG.64 (8B-aligned: row base even, x multiple of 4)
        float* op = obase + r * W_OUT;
        *(float2*)op = make_float2(K * o0, K * o1);
        if (full) *(float2*)(op + 2) = make_float2(K * o2, K * o3);
    }
}

extern "C" void kernel_launch(void* const* d_in, const int* in_sizes, int n_in,
                              void* d_out, int out_size) {
    const float* inp = (const float*)d_in[0];
    const float* kw  = (const float*)d_in[1];
    float* out = (float*)d_out;

    // Host-side linear LIF gain (double precision), I = 1:
    //   v' = v + (-v + R*I) / (R*C) * DT ; vt averaged per reference
    const double R = 3000.0;
    const double C = 10.0;
    const double DT = (double)0.01f;   // reference uses float32 DT
    const double NSTEPS = 1000.0;

    double v = 0.0;
    v = v + (-v + R * 1.0) / (R * C) * DT;   // v0
    double vt = v;
    for (int i = 0; i < 999; i++) {
        v = v + (-v + R * 1.0) / (R * C) * DT;
        vt = (v + vt) / NSTEPS;
    }
    float K = (float)vt;

    // Stage the 3x3 weights into __constant__ (device-to-device, capturable).
    cudaMemcpyToSymbolAsync(c_kw, kw, 9 * sizeof(float), 0,
                            cudaMemcpyDeviceToDevice, 0);

    dim3 block(TPB, 1, 1);
    dim3 grid(1, H_OUT / ROWS, BATCH);   // 1 x 34 x 64 = 2176 blocks (one wave)
    snn_conv_kernel<<<grid, block>>>(inp, out, K);
}